// round 1
// baseline (speedup 1.0000x reference)
#include <cuda_runtime.h>
#include <cuda_bf16.h>
#include <cstdint>

// LUTBlock: out[b,o] = sum_{t=0..15} table[t, idx[b,t], o]
// idx[b,t] = sum_c ((x[b, aa[t,c]] - x[b, ab[t,c]]) > 0) << c
// (the soft/straight-through term in the reference is exactly zero in forward)

#define B_SZ    16384
#define IN_F    1024
#define OUT_F   1024
#define T_CNT   16
#define C_CNT   8
#define R_CNT   256

__global__ __launch_bounds__(256, 8)
void lut_gather_sum_kernel(const float* __restrict__ x,
                           const float4* __restrict__ table4,
                           const int* __restrict__ aa,
                           const int* __restrict__ ab,
                           float4* __restrict__ out4)
{
    __shared__ int s_idx[T_CNT];

    const int b   = blockIdx.x;
    const int tid = threadIdx.x;

    // Phase 1: lanes 0..15 (warp 0) compute the 16 hard indices for this batch.
    if (tid < T_CNT) {
        const float* xr = x + (size_t)b * IN_F;
        int bits = 0;
#pragma unroll
        for (int c = 0; c < C_CNT; c++) {
            const int ia = __ldg(&aa[tid * C_CNT + c]);
            const int ib = __ldg(&ab[tid * C_CNT + c]);
            const float d = __ldg(&xr[ia]) - __ldg(&xr[ib]);
            bits |= (d > 0.0f) ? (1 << c) : 0;
        }
        s_idx[tid] = bits;
    }
    __syncthreads();

    // Phase 2: each thread owns one float4 column group (OUT_F/4 == 256 == blockDim.x).
    // 16 independent coalesced LDG.128 from the L2-resident table, accumulated fp32.
    float4 acc = make_float4(0.f, 0.f, 0.f, 0.f);
#pragma unroll
    for (int t = 0; t < T_CNT; t++) {
        const int r = s_idx[t];
        const float4 v = __ldg(&table4[(((size_t)(t << 8) + r) << 8) + tid]);
        acc.x += v.x;
        acc.y += v.y;
        acc.z += v.z;
        acc.w += v.w;
    }

    out4[(size_t)b * (OUT_F / 4) + tid] = acc;
}

extern "C" void kernel_launch(void* const* d_in, const int* in_sizes, int n_in,
                              void* d_out, int out_size)
{
    const float*  x      = (const float*) d_in[0];  // (B, IN_F) fp32
    const float4* table4 = (const float4*)d_in[1];  // (T, R, OUT_F) fp32
    const int*    aa     = (const int*)   d_in[2];  // (T, C) int32
    const int*    ab     = (const int*)   d_in[3];  // (T, C) int32
    float4*       out4   = (float4*)      d_out;    // (B, OUT_F) fp32

    (void)in_sizes; (void)n_in; (void)out_size;

    lut_gather_sum_kernel<<<B_SZ, 256>>>(x, table4, aa, ab, out4);
}

// round 2
// speedup vs baseline: 1.0263x; 1.0263x over previous
#include <cuda_runtime.h>
#include <cuda_bf16.h>
#include <cstdint>

// LUTBlock: out[b,o] = sum_{t=0..15} table[t, idx[b,t], o]
// idx[b,t] = sum_c ((x[b, aa[t,c]] - x[b, ab[t,c]]) > 0) << c
// (the soft/straight-through term in the reference is exactly zero in forward)

#define B_SZ    16384
#define IN_F    1024
#define OUT_F   1024
#define T_CNT   16
#define C_CNT   8
#define R_CNT   256

__global__ __launch_bounds__(256, 8)
void lut_gather_sum_kernel(const float* __restrict__ x,
                           const float4* __restrict__ table4,
                           const int* __restrict__ aa,
                           const int* __restrict__ ab,
                           float4* __restrict__ out4)
{
    __shared__ int s_idx[T_CNT];

    const int b   = blockIdx.x;
    const int tid = threadIdx.x;

    // Phase 1: lanes 0..15 (warp 0) compute the 16 hard indices for this batch.
    if (tid < T_CNT) {
        const float* xr = x + (size_t)b * IN_F;
        int bits = 0;
#pragma unroll
        for (int c = 0; c < C_CNT; c++) {
            const int ia = __ldg(&aa[tid * C_CNT + c]);
            const int ib = __ldg(&ab[tid * C_CNT + c]);
            const float d = __ldg(&xr[ia]) - __ldg(&xr[ib]);
            bits |= (d > 0.0f) ? (1 << c) : 0;
        }
        s_idx[tid] = bits;
    }
    __syncthreads();

    // Phase 2: each thread owns one float4 column group (OUT_F/4 == 256 == blockDim.x).
    // 16 independent coalesced LDG.128 from the L2-resident table, accumulated fp32.
    float4 acc = make_float4(0.f, 0.f, 0.f, 0.f);
#pragma unroll
    for (int t = 0; t < T_CNT; t++) {
        const int r = s_idx[t];
        const float4 v = __ldg(&table4[(((size_t)(t << 8) + r) << 8) + tid]);
        acc.x += v.x;
        acc.y += v.y;
        acc.z += v.z;
        acc.w += v.w;
    }

    out4[(size_t)b * (OUT_F / 4) + tid] = acc;
}

extern "C" void kernel_launch(void* const* d_in, const int* in_sizes, int n_in,
                              void* d_out, int out_size)
{
    const float*  x      = (const float*) d_in[0];  // (B, IN_F) fp32
    const float4* table4 = (const float4*)d_in[1];  // (T, R, OUT_F) fp32
    const int*    aa     = (const int*)   d_in[2];  // (T, C) int32
    const int*    ab     = (const int*)   d_in[3];  // (T, C) int32
    float4*       out4   = (float4*)      d_out;    // (B, OUT_F) fp32

    (void)in_sizes; (void)n_in; (void)out_size;

    lut_gather_sum_kernel<<<B_SZ, 256>>>(x, table4, aa, ab, out4);
}

// round 3
// speedup vs baseline: 1.1666x; 1.1366x over previous
#include <cuda_runtime.h>
#include <cuda_fp16.h>
#include <cstdint>

// LUTBlock: out[b,o] = sum_{t=0..15} table[t, idx[b,t], o]
// idx[b,t] = sum_c ((x[b, aa[t,c]] - x[b, ab[t,c]]) > 0) << c
// (soft/straight-through term in the reference is exactly zero in forward)
//
// R3: table converted to fp16 scratch once per launch -> halves L2/L1 table
// bytes (1.07 GB -> 537 MB), fp32 accumulation. Expected rel_err ~3e-4.

#define B_SZ    16384
#define IN_F    1024
#define OUT_F   1024
#define T_CNT   16
#define C_CNT   8
#define R_CNT   256

#define TABLE_ELEMS (T_CNT * R_CNT * OUT_F)   // 4M elements

// 8 MB fp16 scratch copy of the table (device global: allocation-free).
__device__ __half g_table_h[TABLE_ELEMS];

// ---------------------------------------------------------------------------
// Pre-pass: fp32 table -> fp16 scratch. 4M elems, float4 in / half2x2 out.
// ---------------------------------------------------------------------------
__global__ __launch_bounds__(256)
void convert_table_kernel(const float4* __restrict__ table4)
{
    const int i = blockIdx.x * blockDim.x + threadIdx.x;   // 0 .. 1M-1
    const float4 v = __ldg(&table4[i]);
    half2* dst = reinterpret_cast<half2*>(g_table_h) + 2 * i;
    dst[0] = __floats2half2_rn(v.x, v.y);
    dst[1] = __floats2half2_rn(v.z, v.w);
}

// ---------------------------------------------------------------------------
// Main: one CTA per batch; thread tid owns output floats [4*tid, 4*tid+4).
// ---------------------------------------------------------------------------
__global__ __launch_bounds__(256, 8)
void lut_gather_sum_h_kernel(const float* __restrict__ x,
                             const int* __restrict__ aa,
                             const int* __restrict__ ab,
                             float4* __restrict__ out4)
{
    __shared__ int s_idx[T_CNT];

    const int b   = blockIdx.x;
    const int tid = threadIdx.x;

    // Phase 1: lanes 0..15 compute the 16 hard indices for this batch.
    if (tid < T_CNT) {
        const float* xr = x + (size_t)b * IN_F;
        int bits = 0;
#pragma unroll
        for (int c = 0; c < C_CNT; c++) {
            const int ia = __ldg(&aa[tid * C_CNT + c]);
            const int ib = __ldg(&ab[tid * C_CNT + c]);
            const float d = __ldg(&xr[ia]) - __ldg(&xr[ib]);
            bits |= (d > 0.0f) ? (1 << c) : 0;
        }
        s_idx[tid] = bits;
    }
    __syncthreads();

    // Phase 2: 16 independent coalesced 8-byte loads (4 halves each) from the
    // fp16 table, fp32 accumulation.
    const uint2* th = reinterpret_cast<const uint2*>(g_table_h);

    float4 acc = make_float4(0.f, 0.f, 0.f, 0.f);
#pragma unroll
    for (int t = 0; t < T_CNT; t++) {
        const int r = s_idx[t];
        // row (t*256 + r) has OUT_F/4 = 256 uint2 groups
        const uint2 v = __ldg(&th[(((t << 8) + r) << 8) + tid]);
        const half2 h0 = *reinterpret_cast<const half2*>(&v.x);
        const half2 h1 = *reinterpret_cast<const half2*>(&v.y);
        const float2 f0 = __half22float2(h0);
        const float2 f1 = __half22float2(h1);
        acc.x += f0.x;
        acc.y += f0.y;
        acc.z += f1.x;
        acc.w += f1.y;
    }

    out4[(size_t)b * (OUT_F / 4) + tid] = acc;
}

extern "C" void kernel_launch(void* const* d_in, const int* in_sizes, int n_in,
                              void* d_out, int out_size)
{
    const float*  x      = (const float*) d_in[0];  // (B, IN_F) fp32
    const float4* table4 = (const float4*)d_in[1];  // (T, R, OUT_F) fp32
    const int*    aa     = (const int*)   d_in[2];  // (T, C) int32
    const int*    ab     = (const int*)   d_in[3];  // (T, C) int32
    float4*       out4   = (float4*)      d_out;    // (B, OUT_F) fp32

    (void)in_sizes; (void)n_in; (void)out_size;

    // Pre-pass: table -> fp16 scratch (4M elems / 4 per thread / 256 per CTA)
    convert_table_kernel<<<TABLE_ELEMS / 4 / 256, 256>>>(table4);

    // Main gather-sum
    lut_gather_sum_h_kernel<<<B_SZ, 256>>>(x, aa, ab, out4);
}